// round 16
// baseline (speedup 1.0000x reference)
#include <cuda_runtime.h>
#include <cuda_bf16.h>
#include <cuda_fp16.h>
#include <math.h>

#define N_NODES 100000
#define E_EDGES 1600000
#define FDIM    128
#define GGRAPHS 64
#define COUT    10
#define SCAN_B  ((N_NODES + 255) / 256)   // 391

// -------------------- scratch (static device globals) -----------------------
__device__ int   g_deg[N_NODES];
__device__ int   g_rowptr[N_NODES + 1];
__device__ int   g_cursor[N_NODES];
__device__ int   g_csr[E_EDGES];
__device__ unsigned long long g_status[SCAN_B];
__device__ unsigned int g_ticket;
// W fp16, layout [layer][ktile 8][row 256][16 permuted]
__device__ __align__(16) __half g_wh[3 * 256 * FDIM];
// activations fp16; g_h16 permuted-k between layers, linear after layer 3
__device__ __align__(16) __half g_h16[(size_t)N_NODES * FDIM];
__device__ __align__(16) __half g_xrh[(size_t)N_NODES * FDIM];
__device__ __align__(16) __half g_xoh[(size_t)N_NODES * FDIM];

// -------------------- CSR build ---------------------------------------------
__global__ void k_zero_deg() {
    int i = blockIdx.x * blockDim.x + threadIdx.x;
    if (i < N_NODES) g_deg[i] = 0;
    if (i < SCAN_B) g_status[i] = 0ULL;
    if (i == 0) g_ticket = 0u;
}

__global__ void k_hist(const int* __restrict__ ei) {
    int i = blockIdx.x * blockDim.x + threadIdx.x;
    if (i < E_EDGES / 4) {
        int4 d = __ldg((const int4*)(ei + E_EDGES) + i);
        atomicAdd(&g_deg[d.x], 1);
        atomicAdd(&g_deg[d.y], 1);
        atomicAdd(&g_deg[d.z], 1);
        atomicAdd(&g_deg[d.w], 1);
    }
}

// single-pass decoupled-lookback exclusive scan of g_deg -> g_rowptr/g_cursor
__global__ void k_scan_lb() {
    __shared__ int s[256];
    __shared__ int sbid;
    __shared__ int sprev;
    int tid = threadIdx.x;
    if (tid == 0) sbid = (int)atomicAdd(&g_ticket, 1u);
    __syncthreads();
    int bid = sbid;
    int i = bid * 256 + tid;
    int v = (i < N_NODES) ? g_deg[i] : 0;
    s[tid] = v;
    __syncthreads();
    for (int d = 1; d < 256; d <<= 1) {
        int t = (tid >= d) ? s[tid - d] : 0;
        __syncthreads();
        s[tid] += t;
        __syncthreads();
    }
    int total = s[255];
    if (tid == 0) {
        if (bid == 0) {
            atomicExch(&g_status[0], (2ULL << 62) | (unsigned)total);
            sprev = 0;
        } else {
            atomicExch(&g_status[bid], (1ULL << 62) | (unsigned)total);
            int running = 0;
            int j = bid - 1;
            while (j >= 0) {
                unsigned long long st = atomicAdd(&g_status[j], 0ULL);
                unsigned long long flag = st >> 62;
                if (flag == 2ULL) { running += (int)(st & 0xffffffffULL); break; }
                if (flag == 1ULL) { running += (int)(st & 0xffffffffULL); j--; }
                // flag 0: spin
            }
            atomicExch(&g_status[bid], (2ULL << 62) | (unsigned)(running + total));
            sprev = running;
        }
    }
    __syncthreads();
    int excl = sprev + s[tid] - v;
    if (i < N_NODES) {
        g_rowptr[i] = excl;
        g_cursor[i] = excl;
        if (i == N_NODES - 1) g_rowptr[N_NODES] = excl + v;
    }
}

__global__ void k_fill(const int* __restrict__ ei) {
    int i = blockIdx.x * blockDim.x + threadIdx.x;
    if (i < E_EDGES / 4) {
        int4 s = __ldg((const int4*)ei + i);
        int4 d = __ldg((const int4*)(ei + E_EDGES) + i);
        int p;
        p = atomicAdd(&g_cursor[d.x], 1); g_csr[p] = s.x;
        p = atomicAdd(&g_cursor[d.y], 1); g_csr[p] = s.y;
        p = atomicAdd(&g_cursor[d.z], 1); g_csr[p] = s.z;
        p = atomicAdd(&g_cursor[d.w], 1); g_csr[p] = s.w;
    }
}

// -------------------- prep: W fp16 (tile-major, permuted), 3 layers ---------
__global__ void k_conv_w(const float* __restrict__ W1r, const float* __restrict__ W1o,
                         const float* __restrict__ W2r, const float* __restrict__ W2o,
                         const float* __restrict__ W3r, const float* __restrict__ W3o) {
    int layer = blockIdx.x >> 8;
    int row = blockIdx.x & 255;     // 0..255 (0-127 Wr, 128-255 Wo)
    int k = threadIdx.x;            // 0..127
    const float* Wr = (layer == 0) ? W1r : (layer == 1) ? W2r : W3r;
    const float* Wo = (layer == 0) ? W1o : (layer == 1) ? W2o : W3o;
    const float* src = (row < 128) ? (Wr + (size_t)row * FDIM)
                                   : (Wo + (size_t)(row - 128) * FDIM);
    float v = src[k];
    int tile = k >> 4, kk = k & 15;
    int p = 4 * ((kk & 7) >> 1) + 2 * ((kk >> 3) & 1) + (kk & 1);
    g_wh[layer * 256 * FDIM + tile * 4096 + row * 16 + p] = __float2half(v);
}

// ===================== dual fp16 GEMM =======================================
// A source: g_h16 (permuted fp16) normally; layer 0 reads fp32 x directly
// (convert at smem-store). sel=0 warps: xr -> g_xrh; sel=1: xo -> g_xoh.
__device__ __forceinline__ void mma16h(float* c, const unsigned* a,
                                       unsigned b0, unsigned b1) {
    asm volatile(
        "mma.sync.aligned.m16n8k16.row.col.f32.f16.f16.f32 "
        "{%0,%1,%2,%3},{%4,%5,%6,%7},{%8,%9},{%0,%1,%2,%3};"
        : "+f"(c[0]), "+f"(c[1]), "+f"(c[2]), "+f"(c[3])
        : "r"(a[0]), "r"(a[1]), "r"(a[2]), "r"(a[3]), "r"(b0), "r"(b1));
}

__global__ __launch_bounds__(256, 2) void k_gemm_dual(
    const float* __restrict__ A32, int layer, int M)
{
    __shared__ __align__(16) __half sA[2][64 * 16];
    __shared__ __align__(16) __half sB[2][256 * 16];

    int tid = threadIdx.x;
    int m0 = blockIdx.x * 64;
    int warp = tid >> 5, lane = tid & 31;
    int wm = warp >> 1;          // 0..3 -> 16-row slice
    int sel = warp & 1;          // 0: Wr -> xrh, 1: Wo -> xoh
    int gq = lane >> 2, t4 = lane & 3;
    bool use32 = (A32 != nullptr);

    const __half* Wh = g_wh + layer * 256 * FDIM;

    // fp16 A staging: threads 0..127 copy one uint4 (8 halves)
    int ar16 = tid >> 1, ac16 = tid & 1;
    bool aok16 = tid < 128 && (m0 + ar16) < M;
    const __half* abase16 = g_h16 + (size_t)(m0 + ar16) * FDIM + ac16 * 8;
    // fp32 A staging: all 256 threads, one float4 (4 floats) each
    int ar32 = tid >> 2, ac32 = tid & 3;
    bool aok32 = (m0 + ar32) < M;
    const float4* abase32 = use32 ?
        ((const float4*)(A32 + (size_t)(m0 + ar32) * FDIM) + ac32) : nullptr;
    int pb32 = (ac32 & 1) * 8 + (ac32 >> 1) * 2;   // permuted pair base

    // B staging: 512 uint4 chunks, 2 per thread
    int wr0 = tid >> 1, wc0 = (tid & 1) * 8;
    int wr1 = (tid + 256) >> 1, wc1 = ((tid + 256) & 1) * 8;

    uint4 va, wb0, wb1;
    float4 va32;
    const uint4 z4 = make_uint4(0, 0, 0, 0);
#define LOADI(i) do {                                                          \
        if (use32) va32 = aok32 ? __ldg(abase32 + (i) * 4)                     \
                                : make_float4(0.f, 0.f, 0.f, 0.f);             \
        else       va   = aok16 ? *(const uint4*)(abase16 + (i) * 16) : z4;    \
        const __half* wt = Wh + (i) * 4096;                                    \
        wb0 = *(const uint4*)(wt + wr0 * 16 + wc0);                            \
        wb1 = *(const uint4*)(wt + wr1 * 16 + wc1);                            \
    } while (0)
#define STOREI(b) do {                                                         \
        if (use32) {                                                           \
            __half2 h1 = __floats2half2_rn(va32.x, va32.y);                    \
            __half2 h2 = __floats2half2_rn(va32.z, va32.w);                    \
            *(unsigned*)(sA[b] + ar32 * 16 + pb32)     = *(unsigned*)&h1;      \
            *(unsigned*)(sA[b] + ar32 * 16 + pb32 + 4) = *(unsigned*)&h2;      \
        } else if (tid < 128) {                                                \
            *(uint4*)(sA[b] + ar16 * 16 + ac16 * 8) = va;                      \
        }                                                                      \
        *(uint4*)(sB[b] + wr0 * 16 + wc0) = wb0;                               \
        *(uint4*)(sB[b] + wr1 * 16 + wc1) = wb1;                               \
    } while (0)

    float acc[16][4];
#pragma unroll
    for (int j = 0; j < 16; j++)
#pragma unroll
        for (int q = 0; q < 4; q++) acc[j][q] = 0.f;

    LOADI(0);
    STOREI(0);
    __syncthreads();

#pragma unroll
    for (int it = 0; it < 8; it++) {
        int cur = it & 1;
        if (it < 7) {
            LOADI(it + 1);
            STOREI(1 - cur);
        }
        int r1 = wm * 16 + gq;
        uint2 v1 = *(const uint2*)(sA[cur] + r1 * 16 + 4 * t4);
        uint2 v2 = *(const uint2*)(sA[cur] + (r1 + 8) * 16 + 4 * t4);
        unsigned a[4] = {v1.x, v2.x, v1.y, v2.y};
#pragma unroll
        for (int nt = 0; nt < 16; nt++) {
            int n = sel * 128 + nt * 8 + gq;
            uint2 bb = *(const uint2*)(sB[cur] + n * 16 + 4 * t4);
            mma16h(acc[nt], a, bb.x, bb.y);
        }
        __syncthreads();
    }
#undef LOADI
#undef STOREI

    __half* dst = sel ? g_xoh : g_xrh;
    int r0 = m0 + wm * 16 + gq;
#pragma unroll
    for (int nt = 0; nt < 16; nt++) {
        int cc = nt * 8 + t4 * 2;
        if (r0 < M)
            *(__half2*)(dst + (size_t)r0 * FDIM + cc) =
                __floats2half2_rn(acc[nt][0], acc[nt][1]);
        if (r0 + 8 < M)
            *(__half2*)(dst + (size_t)(r0 + 8) * FDIM + cc) =
                __floats2half2_rn(acc[nt][2], acc[nt][3]);
    }
}

// ----- fused: h_i = relu( sum_{j->i} xrh[j] + xoh[i] + bias ) ---------------
// Half-warp (16 lanes) per node, uint4 (8-half) loads per lane, unroll 8.
// mode 0: write permuted fp16 to g_h16 (next GEMM). mode 1: linear fp16.
__global__ void k_agg(const float* __restrict__ bias, int mode)
{
    int node = (blockIdx.x * blockDim.x + threadIdx.x) >> 4;
    if (node >= N_NODES) return;
    int lane = threadIdx.x & 15;
    int beg = g_rowptr[node];
    int end = g_rowptr[node + 1];
    const __half* xr = g_xrh;
    float acc[8];
#pragma unroll
    for (int i = 0; i < 8; i++) acc[i] = 0.f;

#define ACCUM(raw) do {                                                      \
        float2 f0 = __half22float2(*(__half2*)&raw.x);                       \
        float2 f1 = __half22float2(*(__half2*)&raw.y);                       \
        float2 f2 = __half22float2(*(__half2*)&raw.z);                       \
        float2 f3 = __half22float2(*(__half2*)&raw.w);                       \
        acc[0] += f0.x; acc[1] += f0.y; acc[2] += f1.x; acc[3] += f1.y;      \
        acc[4] += f2.x; acc[5] += f2.y; acc[6] += f3.x; acc[7] += f3.y;      \
    } while (0)

    int e = beg;
    for (; e + 8 <= end; e += 8) {
        int s0 = g_csr[e],     s1 = g_csr[e + 1], s2 = g_csr[e + 2], s3 = g_csr[e + 3];
        int s4 = g_csr[e + 4], s5 = g_csr[e + 5], s6 = g_csr[e + 6], s7 = g_csr[e + 7];
        uint4 r0 = __ldg((const uint4*)(xr + (size_t)s0 * FDIM) + lane);
        uint4 r1 = __ldg((const uint4*)(xr + (size_t)s1 * FDIM) + lane);
        uint4 r2 = __ldg((const uint4*)(xr + (size_t)s2 * FDIM) + lane);
        uint4 r3 = __ldg((const uint4*)(xr + (size_t)s3 * FDIM) + lane);
        uint4 r4 = __ldg((const uint4*)(xr + (size_t)s4 * FDIM) + lane);
        uint4 r5 = __ldg((const uint4*)(xr + (size_t)s5 * FDIM) + lane);
        uint4 r6 = __ldg((const uint4*)(xr + (size_t)s6 * FDIM) + lane);
        uint4 r7 = __ldg((const uint4*)(xr + (size_t)s7 * FDIM) + lane);
        ACCUM(r0); ACCUM(r1); ACCUM(r2); ACCUM(r3);
        ACCUM(r4); ACCUM(r5); ACCUM(r6); ACCUM(r7);
    }
    for (; e + 2 <= end; e += 2) {
        int s0 = g_csr[e], s1 = g_csr[e + 1];
        uint4 r0 = __ldg((const uint4*)(xr + (size_t)s0 * FDIM) + lane);
        uint4 r1 = __ldg((const uint4*)(xr + (size_t)s1 * FDIM) + lane);
        ACCUM(r0); ACCUM(r1);
    }
    if (e < end) {
        int s0 = g_csr[e];
        uint4 r0 = __ldg((const uint4*)(xr + (size_t)s0 * FDIM) + lane);
        ACCUM(r0);
    }
#undef ACCUM

    uint4 oraw = __ldg((const uint4*)(g_xoh + (size_t)node * FDIM) + lane);
    float2 o0 = __half22float2(*(__half2*)&oraw.x);
    float2 o1 = __half22float2(*(__half2*)&oraw.y);
    float2 o2 = __half22float2(*(__half2*)&oraw.z);
    float2 o3 = __half22float2(*(__half2*)&oraw.w);
    float4 b0 = __ldg((const float4*)bias + lane * 2);
    float4 b1 = __ldg((const float4*)bias + lane * 2 + 1);
    float r[8];
    r[0] = fmaxf(acc[0] + o0.x + b0.x, 0.f);
    r[1] = fmaxf(acc[1] + o0.y + b0.y, 0.f);
    r[2] = fmaxf(acc[2] + o1.x + b0.z, 0.f);
    r[3] = fmaxf(acc[3] + o1.y + b0.w, 0.f);
    r[4] = fmaxf(acc[4] + o2.x + b1.x, 0.f);
    r[5] = fmaxf(acc[5] + o2.y + b1.y, 0.f);
    r[6] = fmaxf(acc[6] + o3.x + b1.z, 0.f);
    r[7] = fmaxf(acc[7] + o3.y + b1.w, 0.f);

    __half2 p0 = __floats2half2_rn(r[0], r[1]);
    __half2 p1 = __floats2half2_rn(r[2], r[3]);
    __half2 p2 = __floats2half2_rn(r[4], r[5]);
    __half2 p3 = __floats2half2_rn(r[6], r[7]);
    __half* hbase = g_h16 + (size_t)node * FDIM;
    if (mode == 0) {
        int tile = lane >> 1;
        int pos = tile * 16 + ((lane & 1) ? 2 : 0);
        *(unsigned*)(hbase + pos)      = *(unsigned*)&p0;
        *(unsigned*)(hbase + pos + 4)  = *(unsigned*)&p1;
        *(unsigned*)(hbase + pos + 8)  = *(unsigned*)&p2;
        *(unsigned*)(hbase + pos + 12) = *(unsigned*)&p3;
    } else {
        uint4 pk;
        pk.x = *(unsigned*)&p0; pk.y = *(unsigned*)&p1;
        pk.z = *(unsigned*)&p2; pk.w = *(unsigned*)&p3;
        *(uint4*)(hbase + lane * 8) = pk;
    }
}

// -------------------- fused mean-pool + MLP head + log_softmax --------------
__global__ void k_pool_mlp(const int* __restrict__ batch,
                           const float* __restrict__ Wl1, const float* __restrict__ bl1,
                           const float* __restrict__ Wl2, const float* __restrict__ bl2,
                           float* __restrict__ out)
{
    int g = blockIdx.x;
    int t = threadIdx.x;                 // 0..511
    int col = t & 127, stripe = t >> 7;
    __shared__ float red[4][FDIM];
    __shared__ float p[FDIM];
    __shared__ float h1[64];
    __shared__ float lg[COUT];
    int lo, hi;
    {
        int key = g;
        int a = 0, b = N_NODES;
        while (a < b) { int m = (a + b) >> 1; if (batch[m] < key) a = m + 1; else b = m; }
        lo = a;
        key = g + 1; a = lo; b = N_NODES;
        while (a < b) { int m = (a + b) >> 1; if (batch[m] < key) a = m + 1; else b = m; }
        hi = a;
    }
    float s = 0.f;
    for (int n = lo + stripe; n < hi; n += 4)
        s += __half2float(g_h16[(size_t)n * FDIM + col]);
    red[stripe][col] = s;
    __syncthreads();
    if (stripe == 0) {
        float tot = red[0][col] + red[1][col] + red[2][col] + red[3][col];
        float c = (float)max(hi - lo, 1);
        p[col] = tot / c;
    }
    __syncthreads();
    if (t < 64) {
        float s1 = bl1[t];
#pragma unroll 8
        for (int k = 0; k < FDIM; k++) s1 += p[k] * Wl1[t * FDIM + k];
        h1[t] = fmaxf(s1, 0.f);
    }
    __syncthreads();
    if (t < COUT) {
        float s2 = bl2[t];
#pragma unroll 8
        for (int k = 0; k < 64; k++) s2 += h1[k] * Wl2[t * 64 + k];
        lg[t] = s2;
    }
    __syncthreads();
    if (t == 0) {
        float mx = -INFINITY;
        for (int c = 0; c < COUT; c++) mx = fmaxf(mx, lg[c]);
        float se = 0.f;
        for (int c = 0; c < COUT; c++) se += expf(lg[c] - mx);
        float lse = logf(se) + mx;
        for (int c = 0; c < COUT; c++) out[g * COUT + c] = lg[c] - lse;
    }
}

// -------------------- launch ------------------------------------------------
extern "C" void kernel_launch(void* const* d_in, const int* in_sizes, int n_in,
                              void* d_out, int out_size)
{
    const float* x     = (const float*)d_in[0];
    const int*   ei    = (const int*)d_in[1];
    const int*   batch = (const int*)d_in[2];
    int wb = 3;
    if (n_in > 3 && in_sizes[3] <= 4) wb = 4;
    const float* W1r = (const float*)d_in[wb + 0];
    const float* b1  = (const float*)d_in[wb + 1];
    const float* W1o = (const float*)d_in[wb + 2];
    const float* W2r = (const float*)d_in[wb + 3];
    const float* b2  = (const float*)d_in[wb + 4];
    const float* W2o = (const float*)d_in[wb + 5];
    const float* W3r = (const float*)d_in[wb + 6];
    const float* b3  = (const float*)d_in[wb + 7];
    const float* W3o = (const float*)d_in[wb + 8];
    const float* Wl1 = (const float*)d_in[wb + 9];
    const float* bl1 = (const float*)d_in[wb + 10];
    const float* Wl2 = (const float*)d_in[wb + 11];
    const float* bl2 = (const float*)d_in[wb + 12];
    float* out = (float*)d_out;

    // one-time side stream + fork/join events (host resources only)
    static cudaStream_t s2 = nullptr;
    static cudaEvent_t evFork = nullptr, evJoin = nullptr;
    if (s2 == nullptr) {
        cudaStreamCreateWithFlags(&s2, cudaStreamNonBlocking);
        cudaEventCreateWithFlags(&evFork, cudaEventDisableTiming);
        cudaEventCreateWithFlags(&evJoin, cudaEventDisableTiming);
    }

    // ---- fork: CSR build on s2, prep + layer-1 GEMM on main stream ----
    cudaEventRecord(evFork, 0);
    cudaStreamWaitEvent(s2, evFork, 0);

    k_zero_deg<<<(N_NODES + 255) / 256, 256, 0, s2>>>();
    k_hist<<<(E_EDGES / 4 + 255) / 256, 256, 0, s2>>>(ei);
    k_scan_lb<<<SCAN_B, 256, 0, s2>>>();
    k_fill<<<(E_EDGES / 4 + 255) / 256, 256, 0, s2>>>(ei);
    cudaEventRecord(evJoin, s2);

    int gemmBlocks = (N_NODES + 63) / 64;
    int aggBlocks  = (N_NODES * 16 + 255) / 256;

    k_conv_w<<<768, 128>>>(W1r, W1o, W2r, W2o, W3r, W3o);
    k_gemm_dual<<<gemmBlocks, 256>>>(x, 0, N_NODES);    // fp32 A path

    // ---- join: agg needs CSR ----
    cudaStreamWaitEvent(0, evJoin, 0);

    // layer 1
    k_agg<<<aggBlocks, 256>>>(b1, 0);
    // layer 2
    k_gemm_dual<<<gemmBlocks, 256>>>(nullptr, 1, N_NODES);
    k_agg<<<aggBlocks, 256>>>(b2, 0);
    // layer 3
    k_gemm_dual<<<gemmBlocks, 256>>>(nullptr, 2, N_NODES);
    k_agg<<<aggBlocks, 256>>>(b3, 1);

    // fused pool + head
    k_pool_mlp<<<GGRAPHS, 512>>>(batch, Wl1, bl1, Wl2, bl2, out);
}